// round 3
// baseline (speedup 1.0000x reference)
#include <cuda_runtime.h>
#include <cstdint>
#include <cstddef>

// Problem constants (fixed by the reference)
#define E_N   1000000
#define V_N   200000
#define D_N   128
#define FE_N  16
#define DIN   145          // D + Fe + 1
#define DINP  160          // padded K for GEMM1
#define HM    256
#define HAG   256
#define HA    256

// Scratch: aggregation buffer [V, HAG] (device global — allocation-free rule)
__device__ float g_agg[(size_t)V_N * HAG];

// ---------------- packed f32x2 helpers (Blackwell FFMA2 path) ----------------
__device__ __forceinline__ unsigned long long pack2(float lo, float hi) {
    unsigned long long r;
    asm("mov.b64 %0, {%1, %2};" : "=l"(r)
        : "r"(__float_as_uint(lo)), "r"(__float_as_uint(hi)));
    return r;
}
__device__ __forceinline__ void unpack2(unsigned long long v, float& lo, float& hi) {
    unsigned int a, b;
    asm("mov.b64 {%0, %1}, %2;" : "=r"(a), "=r"(b) : "l"(v));
    lo = __uint_as_float(a);
    hi = __uint_as_float(b);
}
__device__ __forceinline__ void fma2(unsigned long long& d,
                                     unsigned long long a, unsigned long long b) {
    asm("fma.rn.f32x2 %0, %1, %2, %0;" : "+l"(d) : "l"(a), "l"(b));
}

// fast log-sigmoid: min(x,0) - log(1 + exp(-|x|)); abs err ~1e-7, fine vs 1e-3 tol
__device__ __forceinline__ float lsig(float x) {
    return fminf(x, 0.0f) - __logf(1.0f + __expf(-fabsf(x)));
}

// ---------------- zero the aggregation buffer ----------------
__global__ void zero_agg_kernel() {
    size_t idx = (size_t)blockIdx.x * blockDim.x + threadIdx.x;  // one float4 each
    reinterpret_cast<float4*>(g_agg)[idx] = make_float4(0.f, 0.f, 0.f, 0.f);
}

// ---------------- shared GEMM tile: [64 rows x 256 cols], 256 threads ----------------
// Thread tile: 8 rows x 8 cols (cols paired for FFMA2). jg=tid&31 -> j0=8*jg,
// eg=tid>>5 -> e0=8*eg. ws chunk layout: ws[kk*264 + j].
template <int KTOT, int KVALID, int XSTR>
__device__ __forceinline__ void gemm_tile_256(
    const float* __restrict__ Wg, int wld,
    const float* xbuf, float* ws,
    unsigned long long acc[8][4],
    int tid, int e0, int j0)
{
#pragma unroll 1
    for (int kb = 0; kb < KTOT; kb += 16) {
        __syncthreads();   // ws free to overwrite; also covers producer of xbuf on iter 0
#pragma unroll
        for (int kk = 0; kk < 16; kk++) {
            int k = kb + kk;
            float w = 0.0f;
            if (KVALID == KTOT || k < KVALID) w = __ldg(Wg + (size_t)tid * wld + k);
            ws[kk * 264 + tid] = w;
        }
        __syncthreads();
#pragma unroll
        for (int kk = 0; kk < 16; kk++) {
            unsigned long long b2[4];
#pragma unroll
            for (int u = 0; u < 4; u++)
                b2[u] = *reinterpret_cast<const unsigned long long*>(ws + kk * 264 + j0 + 2 * u);
#pragma unroll
            for (int i = 0; i < 8; i++) {
                float a = xbuf[(e0 + i) * XSTR + kb + kk];   // warp-broadcast LDS
                unsigned long long a2 = pack2(a, a);
#pragma unroll
                for (int u = 0; u < 4; u++) fma2(acc[i][u], a2, b2[u]);
            }
        }
    }
}

// ---------------- edge kernel: X -> MLP(145,256,256) -> scatter-add ----------------
// smem (floats): xs[64][164] @0 (10496) | h1[64][260] @10496 (16640) |
//                ws[16][264] @27136 (4224) | svi[64] @31360  => 125696 bytes
#define EDGE_SMEM_FLOATS 31424
#define EDGE_SMEM_BYTES  (EDGE_SMEM_FLOATS * 4)

__global__ __launch_bounds__(256, 1) void edge_kernel(
    const float* __restrict__ vs, const float* __restrict__ ef,
    const float* __restrict__ sol, const float* __restrict__ W1m,
    const float* __restrict__ b1m, const float* __restrict__ W2m,
    const int* __restrict__ vidx, const int* __restrict__ esign)
{
    extern __shared__ float sm[];
    float* xs = sm;                 // [64][164]
    float* h1 = sm + 10496;        // [64][260]
    float* ws = sm + 27136;        // [16][264]
    int*   svi = (int*)(sm + 31360);

    const int tid = threadIdx.x;
    const int ebase = blockIdx.x * 64;

    // ---- stage X tile into smem ----
#pragma unroll
    for (int it = 0; it < 8; it++) {                 // 64 rows x 32 float4 of state
        int idx = tid + it * 256;
        int e = idx >> 5, c = idx & 31;
        float4 v = __ldg(reinterpret_cast<const float4*>(vs + (size_t)(ebase + e) * D_N) + c);
        float* row = xs + e * 164 + c * 4;
        row[0] = v.x; row[1] = v.y; row[2] = v.z; row[3] = v.w;
    }
    {                                                // 64 rows x 4 float4 of edge feature
        int e = tid >> 2, c = tid & 3;
        float4 v = __ldg(reinterpret_cast<const float4*>(ef + (size_t)(ebase + e) * FE_N) + c);
        float* row = xs + e * 164 + D_N + c * 4;
        row[0] = v.x; row[1] = v.y; row[2] = v.z; row[3] = v.w;
    }
    if (tid < 64) {                                  // signed solution + zero pad
        int e = tid;
        int vi = __ldg(vidx + ebase + e);
        svi[e] = vi;
        float sg = (float)__ldg(esign + ebase + e);
        xs[e * 164 + 144] = sg * __ldg(sol + vi);
#pragma unroll
        for (int k = DIN; k < DINP; k++) xs[e * 164 + k] = 0.0f;
    }

    const int jg = tid & 31, eg = tid >> 5;
    const int j0 = jg * 8, e0 = eg * 8;

    float bias[8];
#pragma unroll
    for (int jj = 0; jj < 8; jj++) bias[jj] = __ldg(b1m + j0 + jj);

    // ---- GEMM1: h1 = lsig(X @ W1m^T + b1m) ----
    unsigned long long acc[8][4];
#pragma unroll
    for (int i = 0; i < 8; i++)
#pragma unroll
        for (int u = 0; u < 4; u++) acc[i][u] = 0ull;

    gemm_tile_256<DINP, DIN, 164>(W1m, DIN, xs, ws, acc, tid, e0, j0);

#pragma unroll
    for (int i = 0; i < 8; i++) {
        float* hrow = h1 + (e0 + i) * 260 + j0;
#pragma unroll
        for (int u = 0; u < 4; u++) {
            float lo, hi;
            unpack2(acc[i][u], lo, hi);
            hrow[2 * u]     = lsig(lo + bias[2 * u]);
            hrow[2 * u + 1] = lsig(hi + bias[2 * u + 1]);
            acc[i][u] = 0ull;   // reset for GEMM2
        }
    }

    // ---- GEMM2: s = lsig(h1 @ W2m^T) ----
    gemm_tile_256<HM, HM, 260>(W2m, HM, h1, ws, acc, tid, e0, j0);

    // ---- epilogue: vector RED scatter into g_agg ----
#pragma unroll
    for (int i = 0; i < 8; i++) {
        float v0, v1, v2, v3, v4, v5, v6, v7;
        unpack2(acc[i][0], v0, v1);
        unpack2(acc[i][1], v2, v3);
        unpack2(acc[i][2], v4, v5);
        unpack2(acc[i][3], v6, v7);
        float4 q0 = make_float4(lsig(v0), lsig(v1), lsig(v2), lsig(v3));
        float4 q1 = make_float4(lsig(v4), lsig(v5), lsig(v6), lsig(v7));
        float* base = g_agg + (size_t)svi[e0 + i] * HAG + j0;
        atomicAdd(reinterpret_cast<float4*>(base), q0);       // sm_90+ vector red
        atomicAdd(reinterpret_cast<float4*>(base + 4), q1);
    }
}

// ---------------- variable kernel: agg -> MLP(256,256,128) -> classifier ----------------
// smem (floats): as[64][260] @0 (16640) | h1[64][260] @16640 (16640) |
//                ws[16][264] @33280 (4224) | h2[64][132] @37504 (8448) => 183808 bytes
#define VAR_SMEM_FLOATS 45952
#define VAR_SMEM_BYTES  (VAR_SMEM_FLOATS * 4)

__global__ __launch_bounds__(256, 1) void var_kernel(
    const float* __restrict__ W1a, const float* __restrict__ b1a,
    const float* __restrict__ W2a, const float* __restrict__ Wc,
    const float* __restrict__ bc, float* __restrict__ out)
{
    extern __shared__ float sm[];
    float* as_ = sm;                // [64][260]
    float* h1  = sm + 16640;       // [64][260]
    float* ws  = sm + 33280;       // [16][264]
    float* h2  = sm + 37504;       // [64][132]

    const int tid = threadIdx.x;
    const int vb = blockIdx.x * 64;

    // load agg tile: 64 x 256 = 64 x 64 float4
#pragma unroll
    for (int it = 0; it < 16; it++) {
        int idx = tid + it * 256;
        int e = idx >> 6, c = idx & 63;
        float4 v = reinterpret_cast<const float4*>(g_agg + (size_t)(vb + e) * HAG)[c];
        float* row = as_ + e * 260 + c * 4;
        row[0] = v.x; row[1] = v.y; row[2] = v.z; row[3] = v.w;
    }

    const int jg = tid & 31, eg = tid >> 5;
    const int j0 = jg * 8, e0 = eg * 8;

    float bias[8];
#pragma unroll
    for (int jj = 0; jj < 8; jj++) bias[jj] = __ldg(b1a + j0 + jj);

    // ---- GEMM1: h1 = lsig(agg @ W1a^T + b1a) ----
    unsigned long long acc[8][4];
#pragma unroll
    for (int i = 0; i < 8; i++)
#pragma unroll
        for (int u = 0; u < 4; u++) acc[i][u] = 0ull;

    gemm_tile_256<HAG, HAG, 260>(W1a, HAG, as_, ws, acc, tid, e0, j0);

#pragma unroll
    for (int i = 0; i < 8; i++) {
        float* hrow = h1 + (e0 + i) * 260 + j0;
#pragma unroll
        for (int u = 0; u < 4; u++) {
            float lo, hi;
            unpack2(acc[i][u], lo, hi);
            hrow[2 * u]     = lsig(lo + bias[2 * u]);
            hrow[2 * u + 1] = lsig(hi + bias[2 * u + 1]);
        }
    }

    // ---- GEMM2: h2 = lsig(h1 @ W2a^T)  [64 x 128] ----
    const int jg2 = tid & 15, eg2 = tid >> 4;
    const int j02 = jg2 * 8, e02 = eg2 * 4;

    unsigned long long acc2[4][4];
#pragma unroll
    for (int i = 0; i < 4; i++)
#pragma unroll
        for (int u = 0; u < 4; u++) acc2[i][u] = 0ull;

#pragma unroll 1
    for (int kb = 0; kb < HA; kb += 16) {
        __syncthreads();
        {
            int j = tid & 127;
            int kh = (tid >> 7) * 8;
#pragma unroll
            for (int q = 0; q < 8; q++)
                ws[(kh + q) * 264 + j] = __ldg(W2a + (size_t)j * HA + kb + kh + q);
        }
        __syncthreads();
#pragma unroll
        for (int kk = 0; kk < 16; kk++) {
            unsigned long long b2[4];
#pragma unroll
            for (int u = 0; u < 4; u++)
                b2[u] = *reinterpret_cast<const unsigned long long*>(ws + kk * 264 + j02 + 2 * u);
#pragma unroll
            for (int i = 0; i < 4; i++) {
                float a = h1[(e02 + i) * 260 + kb + kk];
                unsigned long long a2 = pack2(a, a);
#pragma unroll
                for (int u = 0; u < 4; u++) fma2(acc2[i][u], a2, b2[u]);
            }
        }
    }

#pragma unroll
    for (int i = 0; i < 4; i++) {
        float* hrow = h2 + (e02 + i) * 132 + j02;
#pragma unroll
        for (int u = 0; u < 4; u++) {
            float lo, hi;
            unpack2(acc2[i][u], lo, hi);
            hrow[2 * u]     = lsig(lo);
            hrow[2 * u + 1] = lsig(hi);
        }
    }
    __syncthreads();

    // ---- classifier: out = h2 @ Wc^T + bc  [64 x 2] ----
    if (tid < 128) {
        int e = tid >> 1, p = tid & 1;
        float accv = __ldg(bc + p);
        const float* w = Wc + p * D_N;
        const float* hrow = h2 + e * 132;
#pragma unroll 8
        for (int j = 0; j < D_N; j++) accv = fmaf(hrow[j], __ldg(w + j), accv);
        out[(size_t)(vb + e) * 2 + p] = accv;
    }
}

// ---------------- launch ----------------
extern "C" void kernel_launch(void* const* d_in, const int* in_sizes, int n_in,
                              void* d_out, int out_size)
{
    const float* vs   = (const float*)d_in[0];   // variable_state [E, 128]
    const float* ef   = (const float*)d_in[1];   // edge_feature   [E, 16]
    const float* sol  = (const float*)d_in[2];   // solution       [V]
    const float* W1m  = (const float*)d_in[3];   // [256, 145]
    const float* b1m  = (const float*)d_in[4];   // [256]
    const float* W2m  = (const float*)d_in[5];   // [256, 256]
    const float* W1a  = (const float*)d_in[6];   // [256, 256]
    const float* b1a  = (const float*)d_in[7];   // [256]
    const float* W2a  = (const float*)d_in[8];   // [128, 256]
    const float* Wc   = (const float*)d_in[9];   // [2, 128]
    const float* bc   = (const float*)d_in[10];  // [2]
    const int*  vidx  = (const int*)d_in[11];    // [E]
    const int*  esign = (const int*)d_in[12];    // [E]
    float* out = (float*)d_out;                  // [V, 2]

    cudaFuncSetAttribute(edge_kernel, cudaFuncAttributeMaxDynamicSharedMemorySize, EDGE_SMEM_BYTES);
    cudaFuncSetAttribute(var_kernel,  cudaFuncAttributeMaxDynamicSharedMemorySize, VAR_SMEM_BYTES);

    // g_agg has V*HAG = 51,200,000 floats = 12,800,000 float4 = 50000 blocks x 256
    zero_agg_kernel<<<50000, 256>>>();
    edge_kernel<<<E_N / 64, 256, EDGE_SMEM_BYTES>>>(vs, ef, sol, W1m, b1m, W2m, vidx, esign);
    var_kernel<<<V_N / 64, 256, VAR_SMEM_BYTES>>>(W1a, b1a, W2a, Wc, bc, out);
}